// round 3
// baseline (speedup 1.0000x reference)
#include <cuda_runtime.h>
#include <cstdint>

#define NV 10000
#define NC 100000
#define B  256
#define GRID_MAIN 2960
#define CPB ((NC + GRID_MAIN - 1) / GRID_MAIN)   // 34 clauses per block

// Per clause: uint4 of packed literals. w = (var_index * 128) + neg.
// (row offset in float4 units = var*64 = w>>1 ; neg = w&1). 1.6 MB, L2-resident.
__device__ uint4 g_packed4[NC];
__device__ int g_is64;   // 1 if literal arrays are int64, 0 if int32

// Detect dtype of lit_idx by inspecting odd 32-bit words.
// int64 data (small non-negative values): odd words are high words == 0.
// int32 data: odd words are random indices in [0, NV) -> all-zero ~impossible.
__global__ void detect_k(const unsigned int* __restrict__ lit_idx_raw) {
    unsigned int acc = 0;
    for (int i = 0; i < 128; ++i) acc |= lit_idx_raw[2 * i + 1];
    g_is64 = (acc == 0) ? 1 : 0;
}

__global__ void pack4_k(const unsigned int* __restrict__ idx_raw,
                        const unsigned int* __restrict__ neg_raw) {
    int c = blockIdx.x * blockDim.x + threadIdx.x;
    if (c < NC) {
        int stride = g_is64 ? 2 : 1;
        unsigned int w[3];
        #pragma unroll
        for (int s = 0; s < 3; ++s) {
            unsigned int v = idx_raw[(c * 3 + s) * stride];
            unsigned int n = neg_raw[(c * 3 + s) * stride] & 1u;
            if (v >= NV) v = NV - 1;          // defensive clamp: no OOB ever
            w[s] = v * 128u + n;              // (row_offset_in_float4 << 1) | neg
        }
        g_packed4[c] = make_uint4(w[0], w[1], w[2], w[2]);
    }
}

__global__ void init_k(unsigned int* __restrict__ out) {
    out[threadIdx.x] = 0x7F800000u;   // +inf
}

__device__ __forceinline__ float4 clause_val(uint4 p, const float4* __restrict__ in4, int t) {
    float4 x0 = __ldg(&in4[(p.x >> 1) + t]);
    float4 x1 = __ldg(&in4[(p.y >> 1) + t]);
    float4 x2 = __ldg(&in4[(p.z >> 1) + t]);
    float n0 = (float)(p.x & 1u);
    float n1 = (float)(p.y & 1u);
    float n2 = (float)(p.z & 1u);
    // |n - x| == (n ? 1-x : x) for x in [0,1); FABS folds into FMNMX operands
    float4 r;
    r.x = fmaxf(fmaxf(fabsf(n0 - x0.x), fabsf(n1 - x1.x)), fabsf(n2 - x2.x));
    r.y = fmaxf(fmaxf(fabsf(n0 - x0.y), fabsf(n1 - x1.y)), fabsf(n2 - x2.y));
    r.z = fmaxf(fmaxf(fabsf(n0 - x0.z), fabsf(n1 - x1.z)), fabsf(n2 - x2.z));
    r.w = fmaxf(fmaxf(fabsf(n0 - x0.w), fabsf(n1 - x1.w)), fabsf(n2 - x2.w));
    return r;
}

// 64 threads/block; thread t owns batch elements [4t, 4t+4) via float4 loads.
// Explicit 2-clause pipelining: 6 float4 gathers in flight before consumption.
__global__ void __launch_bounds__(64)
cnf_k(const float* __restrict__ input, unsigned int* __restrict__ out) {
    const int t    = threadIdx.x;
    const int cbeg = blockIdx.x * CPB;
    const int cend = min(cbeg + CPB, NC);
    const float4* __restrict__ in4 = (const float4*)input;

    float4 m = make_float4(__int_as_float(0x7F800000), __int_as_float(0x7F800000),
                           __int_as_float(0x7F800000), __int_as_float(0x7F800000));

    int c = cbeg;
    for (; c + 2 <= cend; c += 2) {
        uint4 pa = __ldg(&g_packed4[c]);
        uint4 pb = __ldg(&g_packed4[c + 1]);
        // issue all 6 gathers up front
        float4 a0 = __ldg(&in4[(pa.x >> 1) + t]);
        float4 a1 = __ldg(&in4[(pa.y >> 1) + t]);
        float4 a2 = __ldg(&in4[(pa.z >> 1) + t]);
        float4 b0 = __ldg(&in4[(pb.x >> 1) + t]);
        float4 b1 = __ldg(&in4[(pb.y >> 1) + t]);
        float4 b2 = __ldg(&in4[(pb.z >> 1) + t]);

        float na0 = (float)(pa.x & 1u), na1 = (float)(pa.y & 1u), na2 = (float)(pa.z & 1u);
        float nb0 = (float)(pb.x & 1u), nb1 = (float)(pb.y & 1u), nb2 = (float)(pb.z & 1u);

        float4 ca, cb;
        ca.x = fmaxf(fmaxf(fabsf(na0 - a0.x), fabsf(na1 - a1.x)), fabsf(na2 - a2.x));
        ca.y = fmaxf(fmaxf(fabsf(na0 - a0.y), fabsf(na1 - a1.y)), fabsf(na2 - a2.y));
        ca.z = fmaxf(fmaxf(fabsf(na0 - a0.z), fabsf(na1 - a1.z)), fabsf(na2 - a2.z));
        ca.w = fmaxf(fmaxf(fabsf(na0 - a0.w), fabsf(na1 - a1.w)), fabsf(na2 - a2.w));
        cb.x = fmaxf(fmaxf(fabsf(nb0 - b0.x), fabsf(nb1 - b1.x)), fabsf(nb2 - b2.x));
        cb.y = fmaxf(fmaxf(fabsf(nb0 - b0.y), fabsf(nb1 - b1.y)), fabsf(nb2 - b2.y));
        cb.z = fmaxf(fmaxf(fabsf(nb0 - b0.z), fabsf(nb1 - b1.z)), fabsf(nb2 - b2.z));
        cb.w = fmaxf(fmaxf(fabsf(nb0 - b0.w), fabsf(nb1 - b1.w)), fabsf(nb2 - b2.w));

        m.x = fminf(m.x, fminf(ca.x, cb.x));
        m.y = fminf(m.y, fminf(ca.y, cb.y));
        m.z = fminf(m.z, fminf(ca.z, cb.z));
        m.w = fminf(m.w, fminf(ca.w, cb.w));
    }
    if (c < cend) {
        uint4 p = __ldg(&g_packed4[c]);
        float4 cv = clause_val(p, in4, t);
        m.x = fminf(m.x, cv.x);
        m.y = fminf(m.y, cv.y);
        m.z = fminf(m.z, cv.z);
        m.w = fminf(m.w, cv.w);
    }

    // uint bit order == float order for non-negative floats
    atomicMin(&out[4 * t + 0], __float_as_uint(m.x));
    atomicMin(&out[4 * t + 1], __float_as_uint(m.y));
    atomicMin(&out[4 * t + 2], __float_as_uint(m.z));
    atomicMin(&out[4 * t + 3], __float_as_uint(m.w));
}

extern "C" void kernel_launch(void* const* d_in, const int* in_sizes, int n_in,
                              void* d_out, int out_size) {
    const float*        input   = (const float*)d_in[0];
    const unsigned int* idx_raw = (const unsigned int*)d_in[1];
    const unsigned int* neg_raw = (const unsigned int*)d_in[2];
    unsigned int*       out     = (unsigned int*)d_out;

    detect_k<<<1, 1>>>(idx_raw);
    pack4_k<<<(NC + 255) / 256, 256>>>(idx_raw, neg_raw);
    init_k<<<1, B>>>(out);
    cnf_k<<<GRID_MAIN, 64>>>(input, out);
}

// round 5
// speedup vs baseline: 2.9583x; 2.9583x over previous
#include <cuda_runtime.h>
#include <cstdint>

#define NV 10000
#define NC 100000
#define B  256
#define GRID_MAIN 1137
#define CPB 88                     // multiple of 4 -> uint4-aligned index groups

// Packed literal: (var_index << 1) | neg_flag, 3 uints per clause. 1.2 MB, L2-resident.
__device__ unsigned int g_packed[NC * 3 + 4];   // +pad so aligned uint4 tail reads are safe
__device__ int g_is64;   // 1 if literal arrays are int64, 0 if int32

// Detect dtype of lit_idx by inspecting odd 32-bit words.
// int64 data (small non-negative values): odd words are all high words == 0.
// int32 data: odd words are random indices in [0, NV) -> all-zero ~impossible.
__global__ void detect_k(const unsigned int* __restrict__ lit_idx_raw) {
    unsigned int acc = 0;
    for (int i = 0; i < 128; ++i) acc |= lit_idx_raw[2 * i + 1];
    g_is64 = (acc == 0) ? 1 : 0;
}

__global__ void pack_k(const unsigned int* __restrict__ idx_raw,
                       const unsigned int* __restrict__ neg_raw) {
    int i = blockIdx.x * blockDim.x + threadIdx.x;
    if (i < NC * 3) {
        int stride = g_is64 ? 2 : 1;
        unsigned int v = idx_raw[i * stride];
        unsigned int n = neg_raw[i * stride] & 1u;
        if (v >= NV) v = NV - 1;              // defensive clamp: no OOB ever
        g_packed[i] = (v << 1) | n;
    }
}

__global__ void init_k(unsigned int* __restrict__ out) {
    out[threadIdx.x] = 0x7F800000u;   // +inf bit pattern
}

// One clause-literal term: |neg - x| == (neg ? 1-x : x) for x in [0,1).
// fabs folds into FMNMX operand modifiers -> 2 FADD + 3 FMNMX per component pair.
__device__ __forceinline__ void clause_acc(float2& m, unsigned int w0, unsigned int w1,
                                           unsigned int w2, float2 x0, float2 x1, float2 x2) {
    float n0 = (float)(w0 & 1u);
    float n1 = (float)(w1 & 1u);
    float n2 = (float)(w2 & 1u);
    float cx = fmaxf(fmaxf(fabsf(n0 - x0.x), fabsf(n1 - x1.x)), fabsf(n2 - x2.x));
    float cy = fmaxf(fmaxf(fabsf(n0 - x0.y), fabsf(n1 - x1.y)), fabsf(n2 - x2.y));
    m.x = fminf(m.x, cx);
    m.y = fminf(m.y, cy);
}

// 128 threads/block; thread t owns batch elements 2t, 2t+1 (float2 loads: warp
// reads 256 contiguous bytes per gather). 4 clauses per iteration: 3 uint4
// index loads + 12 LDG.64 gathers issued before any consumption.
__global__ void __launch_bounds__(128, 8)
cnf_k(const float* __restrict__ input, unsigned int* __restrict__ out) {
    const int t    = threadIdx.x;
    const int cbeg = blockIdx.x * CPB;
    const int cend = min(cbeg + CPB, NC);
    const float2* __restrict__ in2 = (const float2*)input;

    float2 m = make_float2(__int_as_float(0x7F800000), __int_as_float(0x7F800000));

    int c = cbeg;
    for (; c + 4 <= cend; c += 4) {
        // 12 packed literals for 4 clauses; base uint offset c*3 is 16B-aligned
        // (cbeg = 88*b -> 264*b uints, divisible by 4; step 12 preserves it).
        const uint4* q = (const uint4*)&g_packed[c * 3];
        uint4 qa = __ldg(&q[0]);
        uint4 qb = __ldg(&q[1]);
        uint4 qc = __ldg(&q[2]);

        // issue all 12 gathers back-to-back
        float2 x0  = __ldg(&in2[(qa.x >> 1) * (B / 2) + t]);
        float2 x1  = __ldg(&in2[(qa.y >> 1) * (B / 2) + t]);
        float2 x2  = __ldg(&in2[(qa.z >> 1) * (B / 2) + t]);
        float2 x3  = __ldg(&in2[(qa.w >> 1) * (B / 2) + t]);
        float2 x4  = __ldg(&in2[(qb.x >> 1) * (B / 2) + t]);
        float2 x5  = __ldg(&in2[(qb.y >> 1) * (B / 2) + t]);
        float2 x6  = __ldg(&in2[(qb.z >> 1) * (B / 2) + t]);
        float2 x7  = __ldg(&in2[(qb.w >> 1) * (B / 2) + t]);
        float2 x8  = __ldg(&in2[(qc.x >> 1) * (B / 2) + t]);
        float2 x9  = __ldg(&in2[(qc.y >> 1) * (B / 2) + t]);
        float2 x10 = __ldg(&in2[(qc.z >> 1) * (B / 2) + t]);
        float2 x11 = __ldg(&in2[(qc.w >> 1) * (B / 2) + t]);

        clause_acc(m, qa.x, qa.y, qa.z, x0, x1, x2);
        clause_acc(m, qa.w, qb.x, qb.y, x3, x4, x5);
        clause_acc(m, qb.z, qb.w, qc.x, x6, x7, x8);
        clause_acc(m, qc.y, qc.z, qc.w, x9, x10, x11);
    }
    for (; c < cend; ++c) {
        unsigned int w0 = __ldg(&g_packed[c * 3 + 0]);
        unsigned int w1 = __ldg(&g_packed[c * 3 + 1]);
        unsigned int w2 = __ldg(&g_packed[c * 3 + 2]);
        float2 x0 = __ldg(&in2[(w0 >> 1) * (B / 2) + t]);
        float2 x1 = __ldg(&in2[(w1 >> 1) * (B / 2) + t]);
        float2 x2 = __ldg(&in2[(w2 >> 1) * (B / 2) + t]);
        clause_acc(m, w0, w1, w2, x0, x1, x2);
    }

    // uint bit order == float order for non-negative floats
    atomicMin(&out[2 * t + 0], __float_as_uint(m.x));
    atomicMin(&out[2 * t + 1], __float_as_uint(m.y));
}

extern "C" void kernel_launch(void* const* d_in, const int* in_sizes, int n_in,
                              void* d_out, int out_size) {
    const float*        input   = (const float*)d_in[0];
    const unsigned int* idx_raw = (const unsigned int*)d_in[1];
    const unsigned int* neg_raw = (const unsigned int*)d_in[2];
    unsigned int*       out     = (unsigned int*)d_out;

    detect_k<<<1, 1>>>(idx_raw);
    pack_k<<<(NC * 3 + 255) / 256, 256>>>(idx_raw, neg_raw);
    init_k<<<1, B>>>(out);
    cnf_k<<<GRID_MAIN, 128>>>(input, out);
}